// round 9
// baseline (speedup 1.0000x reference)
#include <cuda_runtime.h>
#include <cuda_bf16.h>
#include <math_constants.h>
#include <cstdint>

// ---------------------------------------------------------------------------
// Problem constants
// ---------------------------------------------------------------------------
#define BATCH 4
#define SEQ   2048
#define DMODEL 1024
#define NHEAD 16
#define HEADDIM 64
#define ROWS (BATCH * SEQ)          // 8192
#define QKV_COLS (3 * DMODEL)       // 3072
#define KDIM DMODEL                 // 1024

// ---------------------------------------------------------------------------
// Device scratch (allocation-free per harness rules)
// ---------------------------------------------------------------------------
__device__ float g_qkv[(size_t)ROWS * QKV_COLS];   // [B*L, 3D] fp32
__device__ float g_y[(size_t)ROWS * DMODEL];       // [B*L, D]  fp32

__device__ __nv_bfloat16 g_xa_hi[(size_t)ROWS * KDIM];
__device__ __nv_bfloat16 g_xa_lo[(size_t)ROWS * KDIM];
__device__ __nv_bfloat16 g_ya_hi[(size_t)ROWS * KDIM];
__device__ __nv_bfloat16 g_ya_lo[(size_t)ROWS * KDIM];
// Weights stored K-major (transposed): [N, K]
__device__ __nv_bfloat16 g_wq_hi[(size_t)QKV_COLS * KDIM];
__device__ __nv_bfloat16 g_wq_lo[(size_t)QKV_COLS * KDIM];
__device__ __nv_bfloat16 g_wp_hi[(size_t)DMODEL * KDIM];
__device__ __nv_bfloat16 g_wp_lo[(size_t)DMODEL * KDIM];

// ---------------------------------------------------------------------------
// Arch-neutral tensor-core primitives (sm_80+ PTX; legal on plain sm_103)
// ---------------------------------------------------------------------------
__device__ __forceinline__ uint32_t smem_u32(const void* p) {
    uint32_t a;
    asm("{ .reg .u64 t; cvta.to.shared.u64 t, %1; cvt.u32.u64 %0, t; }"
        : "=r"(a) : "l"(p));
    return a;
}

#define LDSM_X4(r0, r1, r2, r3, addr) \
    asm volatile("ldmatrix.sync.aligned.m8n8.x4.shared.b16 {%0,%1,%2,%3}, [%4];" \
        : "=r"(r0), "=r"(r1), "=r"(r2), "=r"(r3) : "r"(addr))

#define MMA_BF16(d, a, b0, b1) \
    asm volatile("mma.sync.aligned.m16n8k16.row.col.f32.bf16.bf16.f32 " \
        "{%0,%1,%2,%3}, {%4,%5,%6,%7}, {%8,%9}, {%0,%1,%2,%3};" \
        : "+f"((d)[0]), "+f"((d)[1]), "+f"((d)[2]), "+f"((d)[3]) \
        : "r"((a)[0]), "r"((a)[1]), "r"((a)[2]), "r"((a)[3]), "r"(b0), "r"(b1))

// ---------------------------------------------------------------------------
// Prepass: fp32 -> (hi, lo) bf16 split, elementwise
// ---------------------------------------------------------------------------
__global__ __launch_bounds__(256) void split_hilo(
    const float* __restrict__ X, __nv_bfloat16* __restrict__ H,
    __nv_bfloat16* __restrict__ L, int n)
{
    int i = (blockIdx.x * 256 + threadIdx.x) * 4;
    if (i >= n) return;
    float4 v = *(const float4*)(X + i);
    float f[4] = {v.x, v.y, v.z, v.w};
    #pragma unroll
    for (int j = 0; j < 4; j++) {
        __nv_bfloat16 h = __float2bfloat16(f[j]);
        H[i + j] = h;
        L[i + j] = __float2bfloat16(f[j] - __bfloat162float(h));
    }
}

// ---------------------------------------------------------------------------
// Prepass: W[K,N] fp32 -> Th/Tl[N,K] bf16 (transpose + hi/lo split)
// ---------------------------------------------------------------------------
__global__ void transpose_split(
    const float* __restrict__ W, __nv_bfloat16* __restrict__ Th,
    __nv_bfloat16* __restrict__ Tl, int K, int N)
{
    __shared__ float t[32][33];
    const int n0 = blockIdx.x * 32;
    const int k0 = blockIdx.y * 32;
    const int tx = threadIdx.x;   // 0..31
    const int ty = threadIdx.y;   // 0..7
    #pragma unroll
    for (int i = 0; i < 32; i += 8)
        t[ty + i][tx] = W[(size_t)(k0 + ty + i) * N + n0 + tx];
    __syncthreads();
    #pragma unroll
    for (int i = 0; i < 32; i += 8) {
        float f = t[tx][ty + i];
        __nv_bfloat16 h = __float2bfloat16(f);
        __nv_bfloat16 l = __float2bfloat16(f - __bfloat162float(h));
        size_t o = (size_t)(n0 + ty + i) * K + k0 + tx;
        Th[o] = h;
        Tl[o] = l;
    }
}

// ---------------------------------------------------------------------------
// mma.sync GEMM: C[M,N] = (Ahi+Alo)[M,K] @ (Bhi+Blo)[N,K]^T  (split bf16)
// CTA 128x128, 8 warps (warp tile 32x64), K-chunk 64, single-buffer smem,
// 2 CTAs/SM for load/compute overlap.
// ---------------------------------------------------------------------------
#define PADK 72                        // bf16 per smem row (64 data + 8 pad)
#define TILE_ELEMS (128 * PADK)        // per tile
#define GEMM_SMEM (4 * TILE_ELEMS * 2) // Ah, Al, Bh, Bl = 73728 B

__global__ __launch_bounds__(256, 2) void gemm_mma(
    const __nv_bfloat16* __restrict__ Ah, const __nv_bfloat16* __restrict__ Al,
    const __nv_bfloat16* __restrict__ Bh, const __nv_bfloat16* __restrict__ Bl,
    float* __restrict__ C, int N, int K)
{
    extern __shared__ __nv_bfloat16 sm[];
    __nv_bfloat16* tiles[4] = { sm, sm + TILE_ELEMS, sm + 2 * TILE_ELEMS, sm + 3 * TILE_ELEMS };

    const int tid  = threadIdx.x;
    const int wid  = tid >> 5;
    const int lane = tid & 31;
    const int wrow = wid & 3;          // m-tile: 32 rows at wrow*32
    const int wcol = wid >> 2;         // n-tile: 64 cols at wcol*64

    const int brow = blockIdx.y * 128;
    const int bcol = blockIdx.x * 128;

    const __nv_bfloat16* srcs[4] = {
        Ah + (size_t)brow * K, Al + (size_t)brow * K,
        Bh + (size_t)bcol * K, Bl + (size_t)bcol * K };

    // ldmatrix per-thread row/col-offset selectors (see fragment mapping)
    const int rsel = (lane & 7) + ((lane >> 3) & 1) * 8;  // row within 16-block
    const int ksel = ((lane >> 4) & 1) * 8;               // k half (0 or 8)

    const uint32_t sAh = smem_u32(tiles[0]);
    const uint32_t sAl = smem_u32(tiles[1]);
    const uint32_t sBh = smem_u32(tiles[2]);
    const uint32_t sBl = smem_u32(tiles[3]);

    float acc[2][8][4];
    #pragma unroll
    for (int i = 0; i < 2; i++)
        #pragma unroll
        for (int j = 0; j < 8; j++)
            #pragma unroll
            for (int c = 0; c < 4; c++) acc[i][j][c] = 0.f;

    for (int k0 = 0; k0 < K; k0 += 64) {
        // ---- cooperative load: 4 tiles of 128 rows x 64 bf16 ----
        #pragma unroll
        for (int t = 0; t < 4; t++) {
            const __nv_bfloat16* src = srcs[t];
            __nv_bfloat16* dst = tiles[t];
            #pragma unroll
            for (int i = 0; i < 4; i++) {
                int idx = tid + i * 256;           // 1024 x 16B chunks
                int r = idx >> 3, c = idx & 7;
                uint4 v = *(const uint4*)(src + (size_t)r * K + k0 + c * 8);
                *(uint4*)(dst + r * PADK + c * 8) = v;
            }
        }
        __syncthreads();

        // ---- compute: 4 k16 steps ----
        #pragma unroll
        for (int ks = 0; ks < 4; ks++) {
            const int kk = ks * 16 + ksel;
            // A fragments (hi & lo) for two m16 tiles
            uint32_t ah[2][4], al[2][4];
            #pragma unroll
            for (int i = 0; i < 2; i++) {
                uint32_t off = (uint32_t)((wrow * 32 + i * 16 + rsel) * PADK + kk) * 2;
                LDSM_X4(ah[i][0], ah[i][1], ah[i][2], ah[i][3], sAh + off);
                LDSM_X4(al[i][0], al[i][1], al[i][2], al[i][3], sAl + off);
            }
            // B in n16 groups to bound register pressure
            #pragma unroll
            for (int g = 0; g < 4; g++) {
                uint32_t off = (uint32_t)((wcol * 64 + g * 16 + rsel) * PADK + kk) * 2;
                uint32_t bh0, bh1, bh2, bh3, bl0, bl1, bl2, bl3;
                LDSM_X4(bh0, bh1, bh2, bh3, sBh + off);
                LDSM_X4(bl0, bl1, bl2, bl3, sBl + off);
                // tile j=2g: b-frag {r0, r2}; tile j=2g+1: {r1, r3}
                #pragma unroll
                for (int i = 0; i < 2; i++) {
                    MMA_BF16(acc[i][2 * g + 0], ah[i], bh0, bh2);
                    MMA_BF16(acc[i][2 * g + 0], ah[i], bl0, bl2);
                    MMA_BF16(acc[i][2 * g + 0], al[i], bh0, bh2);
                    MMA_BF16(acc[i][2 * g + 1], ah[i], bh1, bh3);
                    MMA_BF16(acc[i][2 * g + 1], ah[i], bl1, bl3);
                    MMA_BF16(acc[i][2 * g + 1], al[i], bh1, bh3);
                }
            }
        }
        __syncthreads();
    }

    // ---- epilogue: fp32 accum -> C (float2 per fragment row) ----
    const int crow0 = brow + wrow * 32 + (lane >> 2);
    const int ccol0 = bcol + wcol * 64 + (lane & 3) * 2;
    #pragma unroll
    for (int i = 0; i < 2; i++) {
        #pragma unroll
        for (int j = 0; j < 8; j++) {
            float* p0 = &C[(size_t)(crow0 + i * 16) * N + ccol0 + j * 8];
            float* p1 = &C[(size_t)(crow0 + i * 16 + 8) * N + ccol0 + j * 8];
            float2 v0 = make_float2(acc[i][j][0], acc[i][j][1]);
            float2 v1 = make_float2(acc[i][j][2], acc[i][j][3]);
            *(float2*)p0 = v0;
            *(float2*)p1 = v1;
        }
    }
}

// ---------------------------------------------------------------------------
// Flash attention (causal, fp32) — unchanged baseline
// ---------------------------------------------------------------------------
#define KPAD 68

__global__ __launch_bounds__(64) void attn_kernel(
    const float* __restrict__ qkv, float* __restrict__ y)
{
    __shared__ float Ks[64][KPAD];
    __shared__ float Vs[64][KPAD];

    const int qtile = blockIdx.x;
    const int bh = blockIdx.y;
    const int b = bh >> 4;
    const int h = bh & 15;
    const int t = threadIdx.x;
    const int qrow = qtile * 64 + t;

    const float scale = 0.125f;

    float q[HEADDIM];
    {
        const float* qp = qkv + ((size_t)(b * SEQ + qrow)) * QKV_COLS + h * HEADDIM;
        #pragma unroll
        for (int d = 0; d < HEADDIM; d += 4) {
            float4 v = *(const float4*)(qp + d);
            q[d] = v.x * scale; q[d+1] = v.y * scale;
            q[d+2] = v.z * scale; q[d+3] = v.w * scale;
        }
    }

    float m = -CUDART_INF_F;
    float l = 0.f;
    float o[HEADDIM];
    #pragma unroll
    for (int d = 0; d < HEADDIM; d++) o[d] = 0.f;

    for (int kt = 0; kt <= qtile; kt++) {
        {
            const float* kp = qkv + ((size_t)(b * SEQ + kt * 64 + t)) * QKV_COLS
                              + DMODEL + h * HEADDIM;
            const float* vp = kp + DMODEL;
            #pragma unroll
            for (int d = 0; d < HEADDIM; d += 4) {
                *(float4*)&Ks[t][d] = *(const float4*)(kp + d);
                *(float4*)&Vs[t][d] = *(const float4*)(vp + d);
            }
        }
        __syncthreads();

        const bool diag = (kt == qtile);

        #pragma unroll 1
        for (int jc = 0; jc < 64; jc += 16) {
            float s[16];
            float cmax = -CUDART_INF_F;
            #pragma unroll
            for (int jj = 0; jj < 16; jj++) {
                const int j = jc + jj;
                float a0 = 0.f, a1 = 0.f;
                #pragma unroll
                for (int d = 0; d < HEADDIM; d += 8) {
                    float4 k0 = *(const float4*)&Ks[j][d];
                    float4 k1 = *(const float4*)&Ks[j][d + 4];
                    a0 = fmaf(q[d+0], k0.x, a0); a0 = fmaf(q[d+1], k0.y, a0);
                    a0 = fmaf(q[d+2], k0.z, a0); a0 = fmaf(q[d+3], k0.w, a0);
                    a1 = fmaf(q[d+4], k1.x, a1); a1 = fmaf(q[d+5], k1.y, a1);
                    a1 = fmaf(q[d+6], k1.z, a1); a1 = fmaf(q[d+7], k1.w, a1);
                }
                float acc = a0 + a1;
                if (diag && (kt * 64 + j > qrow)) acc = -CUDART_INF_F;
                s[jj] = acc;
                cmax = fmaxf(cmax, acc);
            }

            const float mnew = fmaxf(m, cmax);
            const float corr = __expf(m - mnew);
            m = mnew;
            l *= corr;
            #pragma unroll
            for (int d = 0; d < HEADDIM; d++) o[d] *= corr;

            #pragma unroll
            for (int jj = 0; jj < 16; jj++) {
                const int j = jc + jj;
                const float p = __expf(s[jj] - mnew);
                l += p;
                #pragma unroll
                for (int d = 0; d < HEADDIM; d += 4) {
                    float4 vv = *(const float4*)&Vs[j][d];
                    o[d+0] = fmaf(p, vv.x, o[d+0]);
                    o[d+1] = fmaf(p, vv.y, o[d+1]);
                    o[d+2] = fmaf(p, vv.z, o[d+2]);
                    o[d+3] = fmaf(p, vv.w, o[d+3]);
                }
            }
        }
        __syncthreads();
    }

    const float inv = 1.f / l;
    float* yp = y + ((size_t)(b * SEQ + qrow)) * DMODEL + h * HEADDIM;
    #pragma unroll
    for (int d = 0; d < HEADDIM; d += 4) {
        float4 v;
        v.x = o[d+0] * inv; v.y = o[d+1] * inv;
        v.z = o[d+2] * inv; v.w = o[d+3] * inv;
        *(float4*)(yp + d) = v;
    }
}

// ---------------------------------------------------------------------------
// Launch
// ---------------------------------------------------------------------------
extern "C" void kernel_launch(void* const* d_in, const int* in_sizes, int n_in,
                              void* d_out, int out_size)
{
    const float* x     = (const float*)d_in[0];   // [B, L, D]
    const float* Wqkv  = (const float*)d_in[1];   // [D, 3D]
    const float* Wproj = (const float*)d_in[2];   // [D, D]
    float* out = (float*)d_out;                   // [B, L, D]
    (void)in_sizes; (void)n_in; (void)out_size;

    float *qkv, *y;
    __nv_bfloat16 *xah, *xal, *yah, *yal, *wqh, *wql, *wph, *wpl;
    cudaGetSymbolAddress((void**)&qkv, g_qkv);
    cudaGetSymbolAddress((void**)&y, g_y);
    cudaGetSymbolAddress((void**)&xah, g_xa_hi);
    cudaGetSymbolAddress((void**)&xal, g_xa_lo);
    cudaGetSymbolAddress((void**)&yah, g_ya_hi);
    cudaGetSymbolAddress((void**)&yal, g_ya_lo);
    cudaGetSymbolAddress((void**)&wqh, g_wq_hi);
    cudaGetSymbolAddress((void**)&wql, g_wq_lo);
    cudaGetSymbolAddress((void**)&wph, g_wp_hi);
    cudaGetSymbolAddress((void**)&wpl, g_wp_lo);

    cudaFuncSetAttribute(gemm_mma, cudaFuncAttributeMaxDynamicSharedMemorySize, GEMM_SMEM);

    const int nx = ROWS * KDIM;   // 8388608

    // Prepass: split activations, transpose+split weights
    split_hilo<<<nx / 1024, 256>>>(x, xah, xal, nx);
    transpose_split<<<dim3(QKV_COLS / 32, KDIM / 32), dim3(32, 8)>>>(Wqkv, wqh, wql, KDIM, QKV_COLS);
    transpose_split<<<dim3(DMODEL / 32, KDIM / 32), dim3(32, 8)>>>(Wproj, wph, wpl, KDIM, DMODEL);

    // 1) qkv = x @ Wqkv  (mma.sync bf16, split precision)
    gemm_mma<<<dim3(QKV_COLS / 128, ROWS / 128), 256, GEMM_SMEM>>>(
        xah, xal, wqh, wql, qkv, QKV_COLS, KDIM);

    // 2) fused causal attention -> y
    attn_kernel<<<dim3(SEQ / 64, BATCH * NHEAD), 64>>>(qkv, y);

    // 3) out = y @ Wproj  (mma.sync bf16, split precision)
    split_hilo<<<nx / 1024, 256>>>(y, yah, yal, nx);
    gemm_mma<<<dim3(DMODEL / 128, ROWS / 128), 256, GEMM_SMEM>>>(
        yah, yal, wph, wpl, out, DMODEL, KDIM);
}

// round 13
// speedup vs baseline: 3.6261x; 3.6261x over previous
#include <cuda_runtime.h>
#include <cuda_bf16.h>
#include <math_constants.h>
#include <cstdint>

// ---------------------------------------------------------------------------
// Problem constants
// ---------------------------------------------------------------------------
#define BATCH 4
#define SEQ   2048
#define DMODEL 1024
#define NHEAD 16
#define HEADDIM 64
#define ROWS (BATCH * SEQ)          // 8192
#define QKV_COLS (3 * DMODEL)       // 3072
#define KDIM DMODEL                 // 1024

// ---------------------------------------------------------------------------
// Device scratch (allocation-free per harness rules)
// ---------------------------------------------------------------------------
__device__ __nv_bfloat16 g_qkv_hi[(size_t)ROWS * QKV_COLS];
__device__ __nv_bfloat16 g_qkv_lo[(size_t)ROWS * QKV_COLS];
__device__ __nv_bfloat16 g_y_hi[(size_t)ROWS * DMODEL];
__device__ __nv_bfloat16 g_y_lo[(size_t)ROWS * DMODEL];
__device__ __nv_bfloat16 g_xa_hi[(size_t)ROWS * KDIM];
__device__ __nv_bfloat16 g_xa_lo[(size_t)ROWS * KDIM];
// Weights stored K-major (transposed): [N, K]
__device__ __nv_bfloat16 g_wq_hi[(size_t)QKV_COLS * KDIM];
__device__ __nv_bfloat16 g_wq_lo[(size_t)QKV_COLS * KDIM];
__device__ __nv_bfloat16 g_wp_hi[(size_t)DMODEL * KDIM];
__device__ __nv_bfloat16 g_wp_lo[(size_t)DMODEL * KDIM];

// ---------------------------------------------------------------------------
// Arch-neutral tensor-core primitives (sm_80+ PTX; legal on plain sm_103)
// ---------------------------------------------------------------------------
__device__ __forceinline__ uint32_t smem_u32(const void* p) {
    uint32_t a;
    asm("{ .reg .u64 t; cvta.to.shared.u64 t, %1; cvt.u32.u64 %0, t; }"
        : "=r"(a) : "l"(p));
    return a;
}

#define LDSM_X4(r0, r1, r2, r3, addr) \
    asm volatile("ldmatrix.sync.aligned.m8n8.x4.shared.b16 {%0,%1,%2,%3}, [%4];" \
        : "=r"(r0), "=r"(r1), "=r"(r2), "=r"(r3) : "r"(addr))

#define LDSM_X4_T(r0, r1, r2, r3, addr) \
    asm volatile("ldmatrix.sync.aligned.m8n8.x4.trans.shared.b16 {%0,%1,%2,%3}, [%4];" \
        : "=r"(r0), "=r"(r1), "=r"(r2), "=r"(r3) : "r"(addr))

#define MMA_BF16(d, a, b0, b1) \
    asm volatile("mma.sync.aligned.m16n8k16.row.col.f32.bf16.bf16.f32 " \
        "{%0,%1,%2,%3}, {%4,%5,%6,%7}, {%8,%9}, {%0,%1,%2,%3};" \
        : "+f"((d)[0]), "+f"((d)[1]), "+f"((d)[2]), "+f"((d)[3]) \
        : "r"((a)[0]), "r"((a)[1]), "r"((a)[2]), "r"((a)[3]), "r"(b0), "r"(b1))

__device__ __forceinline__ uint32_t pack_bf16(float x, float y) {
    __nv_bfloat162 t = __floats2bfloat162_rn(x, y);   // bits: y<<16 | x
    uint32_t u; *(__nv_bfloat162*)&u = t; return u;
}
__device__ __forceinline__ void split2(float f, __nv_bfloat16& h, __nv_bfloat16& l) {
    h = __float2bfloat16(f);
    l = __float2bfloat16(f - __bfloat162float(h));
}

// ---------------------------------------------------------------------------
// Prepass: fp32 -> (hi, lo) bf16 split, elementwise
// ---------------------------------------------------------------------------
__global__ __launch_bounds__(256) void split_hilo(
    const float* __restrict__ X, __nv_bfloat16* __restrict__ H,
    __nv_bfloat16* __restrict__ L, int n)
{
    int i = (blockIdx.x * 256 + threadIdx.x) * 4;
    if (i >= n) return;
    float4 v = *(const float4*)(X + i);
    float f[4] = {v.x, v.y, v.z, v.w};
    #pragma unroll
    for (int j = 0; j < 4; j++) {
        __nv_bfloat16 h, l; split2(f[j], h, l);
        H[i + j] = h; L[i + j] = l;
    }
}

// ---------------------------------------------------------------------------
// Prepass: W[K,N] fp32 -> Th/Tl[N,K] bf16 (transpose + hi/lo split)
// ---------------------------------------------------------------------------
__global__ void transpose_split(
    const float* __restrict__ W, __nv_bfloat16* __restrict__ Th,
    __nv_bfloat16* __restrict__ Tl, int K, int N)
{
    __shared__ float t[32][33];
    const int n0 = blockIdx.x * 32;
    const int k0 = blockIdx.y * 32;
    const int tx = threadIdx.x;
    const int ty = threadIdx.y;
    #pragma unroll
    for (int i = 0; i < 32; i += 8)
        t[ty + i][tx] = W[(size_t)(k0 + ty + i) * N + n0 + tx];
    __syncthreads();
    #pragma unroll
    for (int i = 0; i < 32; i += 8) {
        float f = t[tx][ty + i];
        __nv_bfloat16 h, l; split2(f, h, l);
        size_t o = (size_t)(n0 + ty + i) * K + k0 + tx;
        Th[o] = h; Tl[o] = l;
    }
}

// ---------------------------------------------------------------------------
// mma.sync GEMM: C = (Ahi+Alo)[M,K] @ (Bhi+Blo)[N,K]^T  (split bf16)
// CTA 128x128, 8 warps (32x64 each), K-chunk 64, 2 CTAs/SM.
// SPLIT_OUT=1: write bf16 hi/lo.  SPLIT_OUT=0: write fp32.
// ---------------------------------------------------------------------------
#define PADK 72
#define TILE_ELEMS (128 * PADK)
#define GEMM_SMEM (4 * TILE_ELEMS * 2)

template<int SPLIT_OUT>
__global__ __launch_bounds__(256, 2) void gemm_mma(
    const __nv_bfloat16* __restrict__ Ah, const __nv_bfloat16* __restrict__ Al,
    const __nv_bfloat16* __restrict__ Bh, const __nv_bfloat16* __restrict__ Bl,
    float* __restrict__ C, __nv_bfloat16* __restrict__ Ch,
    __nv_bfloat16* __restrict__ Cl, int N, int K)
{
    extern __shared__ __nv_bfloat16 sm[];
    __nv_bfloat16* tiles[4] = { sm, sm + TILE_ELEMS, sm + 2 * TILE_ELEMS, sm + 3 * TILE_ELEMS };

    const int tid  = threadIdx.x;
    const int wid  = tid >> 5;
    const int lane = tid & 31;
    const int wrow = wid & 3;
    const int wcol = wid >> 2;

    const int brow = blockIdx.y * 128;
    const int bcol = blockIdx.x * 128;

    const __nv_bfloat16* srcs[4] = {
        Ah + (size_t)brow * K, Al + (size_t)brow * K,
        Bh + (size_t)bcol * K, Bl + (size_t)bcol * K };

    const int rsel = (lane & 15);
    const int ksel = (lane >> 4) * 8;

    const uint32_t sAh = smem_u32(tiles[0]);
    const uint32_t sAl = smem_u32(tiles[1]);
    const uint32_t sBh = smem_u32(tiles[2]);
    const uint32_t sBl = smem_u32(tiles[3]);

    float acc[2][8][4];
    #pragma unroll
    for (int i = 0; i < 2; i++)
        #pragma unroll
        for (int j = 0; j < 8; j++)
            #pragma unroll
            for (int c = 0; c < 4; c++) acc[i][j][c] = 0.f;

    for (int k0 = 0; k0 < K; k0 += 64) {
        #pragma unroll
        for (int t = 0; t < 4; t++) {
            const __nv_bfloat16* src = srcs[t];
            __nv_bfloat16* dst = tiles[t];
            #pragma unroll
            for (int i = 0; i < 4; i++) {
                int idx = tid + i * 256;
                int r = idx >> 3, c = idx & 7;
                uint4 v = *(const uint4*)(src + (size_t)r * K + k0 + c * 8);
                *(uint4*)(dst + r * PADK + c * 8) = v;
            }
        }
        __syncthreads();

        #pragma unroll
        for (int ks = 0; ks < 4; ks++) {
            const int kk = ks * 16 + ksel;
            uint32_t ah[2][4], al[2][4];
            #pragma unroll
            for (int i = 0; i < 2; i++) {
                uint32_t off = (uint32_t)((wrow * 32 + i * 16 + rsel) * PADK + kk) * 2;
                LDSM_X4(ah[i][0], ah[i][1], ah[i][2], ah[i][3], sAh + off);
                LDSM_X4(al[i][0], al[i][1], al[i][2], al[i][3], sAl + off);
            }
            #pragma unroll
            for (int g = 0; g < 4; g++) {
                uint32_t off = (uint32_t)((wcol * 64 + g * 16 + rsel) * PADK + kk) * 2;
                uint32_t bh0, bh1, bh2, bh3, bl0, bl1, bl2, bl3;
                LDSM_X4(bh0, bh1, bh2, bh3, sBh + off);
                LDSM_X4(bl0, bl1, bl2, bl3, sBl + off);
                #pragma unroll
                for (int i = 0; i < 2; i++) {
                    MMA_BF16(acc[i][2 * g + 0], ah[i], bh0, bh2);
                    MMA_BF16(acc[i][2 * g + 0], ah[i], bl0, bl2);
                    MMA_BF16(acc[i][2 * g + 0], al[i], bh0, bh2);
                    MMA_BF16(acc[i][2 * g + 1], ah[i], bh1, bh3);
                    MMA_BF16(acc[i][2 * g + 1], ah[i], bl1, bl3);
                    MMA_BF16(acc[i][2 * g + 1], al[i], bh1, bh3);
                }
            }
        }
        __syncthreads();
    }

    const int crow0 = brow + wrow * 32 + (lane >> 2);
    const int ccol0 = bcol + wcol * 64 + (lane & 3) * 2;
    #pragma unroll
    for (int i = 0; i < 2; i++) {
        #pragma unroll
        for (int j = 0; j < 8; j++) {
            size_t o0 = (size_t)(crow0 + i * 16) * N + ccol0 + j * 8;
            size_t o1 = (size_t)(crow0 + i * 16 + 8) * N + ccol0 + j * 8;
            if (SPLIT_OUT) {
                __nv_bfloat16 h0, l0, h1, l1, h2, l2, h3, l3;
                split2(acc[i][j][0], h0, l0); split2(acc[i][j][1], h1, l1);
                split2(acc[i][j][2], h2, l2); split2(acc[i][j][3], h3, l3);
                *(uint32_t*)&Ch[o0] = pack_bf16(__bfloat162float(h0), __bfloat162float(h1));
                *(uint32_t*)&Cl[o0] = pack_bf16(__bfloat162float(l0), __bfloat162float(l1));
                *(uint32_t*)&Ch[o1] = pack_bf16(__bfloat162float(h2), __bfloat162float(h3));
                *(uint32_t*)&Cl[o1] = pack_bf16(__bfloat162float(l2), __bfloat162float(l3));
            } else {
                *(float2*)&C[o0] = make_float2(acc[i][j][0], acc[i][j][1]);
                *(float2*)&C[o1] = make_float2(acc[i][j][2], acc[i][j][3]);
            }
        }
    }
}

// ---------------------------------------------------------------------------
// Tensor-core flash attention (causal, split bf16, fp32 accum).
// Block: 64 q-rows x one (b,h); 4 warps, each warp 16 q-rows. K-tile 64.
// ---------------------------------------------------------------------------
#define APADK 72
#define ATILE (64 * APADK)           // elems per tile
#define ATTN_SMEM (4 * ATILE * 2)    // Kh,Kl,Vh,Vl = 36864 B

__global__ __launch_bounds__(128) void attn_mma(
    const __nv_bfloat16* __restrict__ qkvh, const __nv_bfloat16* __restrict__ qkvl,
    __nv_bfloat16* __restrict__ Yh, __nv_bfloat16* __restrict__ Yl)
{
    extern __shared__ __nv_bfloat16 asm_[];
    __nv_bfloat16* Kh = asm_;
    __nv_bfloat16* Kl = asm_ + ATILE;
    __nv_bfloat16* Vh = asm_ + 2 * ATILE;
    __nv_bfloat16* Vl = asm_ + 3 * ATILE;
    const uint32_t sKh = smem_u32(Kh), sKl = smem_u32(Kl);
    const uint32_t sVh = smem_u32(Vh), sVl = smem_u32(Vl);

    const int qtile = blockIdx.x;            // 0..31
    const int bh = blockIdx.y;
    const int b = bh >> 4, h = bh & 15;
    const int tid = threadIdx.x, wid = tid >> 5, lane = tid & 31;

    const size_t rowbase = (size_t)b * SEQ;
    const int qcol = h * HEADDIM;
    const int kcol = DMODEL + qcol;
    const int vcol = 2 * DMODEL + qcol;

    // ---- stage Q tile in K buffers, pull into A-fragments, release ----
    for (int i = tid; i < 64 * 8; i += 128) {
        int r = i >> 3, c = i & 7;
        size_t g = (rowbase + qtile * 64 + r) * QKV_COLS + qcol + c * 8;
        *(uint4*)(Kh + r * APADK + c * 8) = *(const uint4*)(qkvh + g);
        *(uint4*)(Kl + r * APADK + c * 8) = *(const uint4*)(qkvl + g);
    }
    __syncthreads();

    uint32_t qfh[4][4], qfl[4][4];
    {
        int r = wid * 16 + (lane & 15);
        int kb = (lane >> 4) * 8;
        #pragma unroll
        for (int ks = 0; ks < 4; ks++) {
            uint32_t off = (uint32_t)(r * APADK + ks * 16 + kb) * 2;
            LDSM_X4(qfh[ks][0], qfh[ks][1], qfh[ks][2], qfh[ks][3], sKh + off);
            LDSM_X4(qfl[ks][0], qfl[ks][1], qfl[ks][2], qfl[ks][3], sKl + off);
        }
    }
    __syncthreads();

    float m0 = -CUDART_INF_F, m1 = -CUDART_INF_F, l0 = 0.f, l1 = 0.f;
    float oacc[8][4];
    #pragma unroll
    for (int j = 0; j < 8; j++)
        #pragma unroll
        for (int c = 0; c < 4; c++) oacc[j][c] = 0.f;

    const int qr0 = qtile * 64 + wid * 16 + (lane >> 2);   // this thread's row 0

    for (int kt = 0; kt <= qtile; kt++) {
        // ---- load K,V hi/lo tiles ----
        for (int i = tid; i < 64 * 8; i += 128) {
            int r = i >> 3, c = i & 7;
            size_t gk = (rowbase + kt * 64 + r) * QKV_COLS + kcol + c * 8;
            size_t gv = (rowbase + kt * 64 + r) * QKV_COLS + vcol + c * 8;
            *(uint4*)(Kh + r * APADK + c * 8) = *(const uint4*)(qkvh + gk);
            *(uint4*)(Kl + r * APADK + c * 8) = *(const uint4*)(qkvl + gk);
            *(uint4*)(Vh + r * APADK + c * 8) = *(const uint4*)(qkvh + gv);
            *(uint4*)(Vl + r * APADK + c * 8) = *(const uint4*)(qkvl + gv);
        }
        __syncthreads();

        // ---- S = Q @ K^T (split 3-term) ----
        float sacc[8][4];
        #pragma unroll
        for (int j = 0; j < 8; j++)
            #pragma unroll
            for (int c = 0; c < 4; c++) sacc[j][c] = 0.f;

        const int bn = (lane & 7) + ((lane >> 4) & 1) * 8;  // K row within 16-group
        const int bkb = ((lane >> 3) & 1) * 8;              // k half
        #pragma unroll
        for (int ks = 0; ks < 4; ks++) {
            #pragma unroll
            for (int np = 0; np < 4; np++) {
                uint32_t off = (uint32_t)((np * 16 + bn) * APADK + ks * 16 + bkb) * 2;
                uint32_t kh0, kh1, kh2, kh3, kl0, kl1, kl2, kl3;
                LDSM_X4(kh0, kh1, kh2, kh3, sKh + off);
                LDSM_X4(kl0, kl1, kl2, kl3, sKl + off);
                MMA_BF16(sacc[2 * np + 0], qfh[ks], kh0, kh1);
                MMA_BF16(sacc[2 * np + 0], qfh[ks], kl0, kl1);
                MMA_BF16(sacc[2 * np + 0], qfl[ks], kh0, kh1);
                MMA_BF16(sacc[2 * np + 1], qfh[ks], kh2, kh3);
                MMA_BF16(sacc[2 * np + 1], qfh[ks], kl2, kl3);
                MMA_BF16(sacc[2 * np + 1], qfl[ks], kh2, kh3);
            }
        }

        // ---- scale, mask, online softmax ----
        const bool diag = (kt == qtile);
        float rmax0 = -CUDART_INF_F, rmax1 = -CUDART_INF_F;
        #pragma unroll
        for (int nt = 0; nt < 8; nt++) {
            #pragma unroll
            for (int c = 0; c < 4; c++) sacc[nt][c] *= 0.125f;
            if (diag) {
                int col = kt * 64 + nt * 8 + (lane & 3) * 2;
                if (col     > qr0    ) sacc[nt][0] = -CUDART_INF_F;
                if (col + 1 > qr0    ) sacc[nt][1] = -CUDART_INF_F;
                if (col     > qr0 + 8) sacc[nt][2] = -CUDART_INF_F;
                if (col + 1 > qr0 + 8) sacc[nt][3] = -CUDART_INF_F;
            }
            rmax0 = fmaxf(rmax0, fmaxf(sacc[nt][0], sacc[nt][1]));
            rmax1 = fmaxf(rmax1, fmaxf(sacc[nt][2], sacc[nt][3]));
        }
        rmax0 = fmaxf(rmax0, __shfl_xor_sync(0xffffffffu, rmax0, 1));
        rmax0 = fmaxf(rmax0, __shfl_xor_sync(0xffffffffu, rmax0, 2));
        rmax1 = fmaxf(rmax1, __shfl_xor_sync(0xffffffffu, rmax1, 1));
        rmax1 = fmaxf(rmax1, __shfl_xor_sync(0xffffffffu, rmax1, 2));

        const float mn0 = fmaxf(m0, rmax0), mn1 = fmaxf(m1, rmax1);
        const float c0 = __expf(m0 - mn0), c1 = __expf(m1 - mn1);
        m0 = mn0; m1 = mn1; l0 *= c0; l1 *= c1;
        #pragma unroll
        for (int nt = 0; nt < 8; nt++) {
            oacc[nt][0] *= c0; oacc[nt][1] *= c0;
            oacc[nt][2] *= c1; oacc[nt][3] *= c1;
        }

        // ---- P = exp(S - m), split hi/lo, pack into A-fragments ----
        uint32_t pfh[4][4], pfl[4][4];
        #pragma unroll
        for (int nt = 0; nt < 8; nt++) {
            float p0 = __expf(sacc[nt][0] - mn0);
            float p1 = __expf(sacc[nt][1] - mn0);
            float p2 = __expf(sacc[nt][2] - mn1);
            float p3 = __expf(sacc[nt][3] - mn1);
            l0 += p0 + p1; l1 += p2 + p3;
            __nv_bfloat16 h0, lo0, h1, lo1, h2, lo2, h3, lo3;
            split2(p0, h0, lo0); split2(p1, h1, lo1);
            split2(p2, h2, lo2); split2(p3, h3, lo3);
            const int ks = nt >> 1;
            const int ro = (nt & 1) * 2;   // even ntile -> a0,a1; odd -> a2,a3
            pfh[ks][ro + 0] = pack_bf16(__bfloat162float(h0), __bfloat162float(h1));
            pfh[ks][ro + 1] = pack_bf16(__bfloat162float(h2), __bfloat162float(h3));
            pfl[ks][ro + 0] = pack_bf16(__bfloat162float(lo0), __bfloat162float(lo1));
            pfl[ks][ro + 1] = pack_bf16(__bfloat162float(lo2), __bfloat162float(lo3));
        }

        // ---- O += P @ V (split 3-term); V via ldmatrix.trans ----
        const int vr = (lane & 7) + ((lane >> 3) & 1) * 8;  // seq row within k16
        const int vc = ((lane >> 4) & 1) * 8;               // col half of 16-group
        #pragma unroll
        for (int ks = 0; ks < 4; ks++) {
            #pragma unroll
            for (int np = 0; np < 4; np++) {
                uint32_t off = (uint32_t)((ks * 16 + vr) * APADK + np * 16 + vc) * 2;
                uint32_t vh0, vh1, vh2, vh3, vl0, vl1, vl2, vl3;
                LDSM_X4_T(vh0, vh1, vh2, vh3, sVh + off);
                LDSM_X4_T(vl0, vl1, vl2, vl3, sVl + off);
                MMA_BF16(oacc[2 * np + 0], pfh[ks], vh0, vh1);
                MMA_BF16(oacc[2 * np + 0], pfh[ks], vl0, vl1);
                MMA_BF16(oacc[2 * np + 0], pfl[ks], vh0, vh1);
                MMA_BF16(oacc[2 * np + 1], pfh[ks], vh2, vh3);
                MMA_BF16(oacc[2 * np + 1], pfh[ks], vl2, vl3);
                MMA_BF16(oacc[2 * np + 1], pfl[ks], vh2, vh3);
            }
        }
        __syncthreads();   // before next tile overwrites K/V
    }

    // ---- finalize: reduce l over quad, normalize, write y hi/lo ----
    l0 += __shfl_xor_sync(0xffffffffu, l0, 1);
    l0 += __shfl_xor_sync(0xffffffffu, l0, 2);
    l1 += __shfl_xor_sync(0xffffffffu, l1, 1);
    l1 += __shfl_xor_sync(0xffffffffu, l1, 2);
    const float inv0 = 1.f / l0, inv1 = 1.f / l1;

    #pragma unroll
    for (int nt = 0; nt < 8; nt++) {
        const int col = h * HEADDIM + nt * 8 + (lane & 3) * 2;
        const size_t o0 = (rowbase + qr0) * DMODEL + col;
        const size_t o1 = (rowbase + qr0 + 8) * DMODEL + col;
        float f0 = oacc[nt][0] * inv0, f1 = oacc[nt][1] * inv0;
        float f2 = oacc[nt][2] * inv1, f3 = oacc[nt][3] * inv1;
        __nv_bfloat16 h0, lo0, h1, lo1, h2, lo2, h3, lo3;
        split2(f0, h0, lo0); split2(f1, h1, lo1);
        split2(f2, h2, lo2); split2(f3, h3, lo3);
        *(uint32_t*)&Yh[o0] = pack_bf16(__bfloat162float(h0), __bfloat162float(h1));
        *(uint32_t*)&Yl[o0] = pack_bf16(__bfloat162float(lo0), __bfloat162float(lo1));
        *(uint32_t*)&Yh[o1] = pack_bf16(__bfloat162float(h2), __bfloat162float(h3));
        *(uint32_t*)&Yl[o1] = pack_bf16(__bfloat162float(lo2), __bfloat162float(lo3));
    }
}

// ---------------------------------------------------------------------------
// Launch
// ---------------------------------------------------------------------------
extern "C" void kernel_launch(void* const* d_in, const int* in_sizes, int n_in,
                              void* d_out, int out_size)
{
    const float* x     = (const float*)d_in[0];
    const float* Wqkv  = (const float*)d_in[1];
    const float* Wproj = (const float*)d_in[2];
    float* out = (float*)d_out;
    (void)in_sizes; (void)n_in; (void)out_size;

    __nv_bfloat16 *qkvh, *qkvl, *yh, *yl, *xah, *xal, *wqh, *wql, *wph, *wpl;
    cudaGetSymbolAddress((void**)&qkvh, g_qkv_hi);
    cudaGetSymbolAddress((void**)&qkvl, g_qkv_lo);
    cudaGetSymbolAddress((void**)&yh, g_y_hi);
    cudaGetSymbolAddress((void**)&yl, g_y_lo);
    cudaGetSymbolAddress((void**)&xah, g_xa_hi);
    cudaGetSymbolAddress((void**)&xal, g_xa_lo);
    cudaGetSymbolAddress((void**)&wqh, g_wq_hi);
    cudaGetSymbolAddress((void**)&wql, g_wq_lo);
    cudaGetSymbolAddress((void**)&wph, g_wp_hi);
    cudaGetSymbolAddress((void**)&wpl, g_wp_lo);

    cudaFuncSetAttribute(gemm_mma<1>, cudaFuncAttributeMaxDynamicSharedMemorySize, GEMM_SMEM);
    cudaFuncSetAttribute(gemm_mma<0>, cudaFuncAttributeMaxDynamicSharedMemorySize, GEMM_SMEM);

    const int nx = ROWS * KDIM;

    split_hilo<<<nx / 1024, 256>>>(x, xah, xal, nx);
    transpose_split<<<dim3(QKV_COLS / 32, KDIM / 32), dim3(32, 8)>>>(Wqkv, wqh, wql, KDIM, QKV_COLS);
    transpose_split<<<dim3(DMODEL / 32, KDIM / 32), dim3(32, 8)>>>(Wproj, wph, wpl, KDIM, DMODEL);

    // 1) qkv = x @ Wqkv -> bf16 hi/lo directly
    gemm_mma<1><<<dim3(QKV_COLS / 128, ROWS / 128), 256, GEMM_SMEM>>>(
        xah, xal, wqh, wql, nullptr, qkvh, qkvl, QKV_COLS, KDIM);

    // 2) tensor-core flash attention -> y hi/lo
    attn_mma<<<dim3(SEQ / 64, BATCH * NHEAD), 128, ATTN_SMEM>>>(qkvh, qkvl, yh, yl);

    // 3) out = y @ Wproj -> fp32
    gemm_mma<0><<<dim3(DMODEL / 128, ROWS / 128), 256, GEMM_SMEM>>>(
        yh, yl, wph, wpl, out, nullptr, nullptr, DMODEL, KDIM);
}